// round 5
// baseline (speedup 1.0000x reference)
#include <cuda_runtime.h>
#include <cuda_bf16.h>
#include <cstdint>

// Inputs (metadata order):
//   d_in[0] = z          float32 [12288, 128]
//   d_in[1] = edge_index int32 [2, 393216] (jnp.int64 silently downcast; detect)
//   d_in[2] = edge_attr  float32 [393216, 4]
//   d_in[3] = W          float32 [1, 256]
//   d_in[4] = b          float32 [1]
// Output: float32 [12288, 12288]
//
// out[r,c] = sum_dup(attr_sum) + (u[r] + v[c] + b) added ONCE per distinct cell.
// Duplicate edges share (r,c) => identical p => any single election winner
// yields the same output, so a plain-store race is a valid (deterministic-
// output) election.

#define N_NODES 12288
#define N_EDGES 393216

#define RESET_BLOCKS 1536   // 1536*256 = 393216 threads, one per edge
#define UV_BLOCKS    1536   // 1536*8 warps = 12288, one warp per node
#define ZERO_BLOCKS  4736   // 148 SMs * 32

// per-cell elected edge id (winner of the plain-store race in prep)
__device__ int g_winner[(size_t)N_NODES * N_NODES];
// per-node partial dots: u[i] = dot(z[i], W[0:128]) + b, v[i] = dot(z[i], W[128:256])
__device__ float g_u[N_NODES];
__device__ float g_v[N_NODES];

// ---------------------------------------------------------------------------
// In-block edge_index dtype detect: if data is int64, the odd int32 words are
// high halves of small non-negative indices => all zero. For int32 data they
// are random indices in [0,12288) — P(32 all zero) ~ 0. Warp-0 ballot.
// ---------------------------------------------------------------------------
__device__ __forceinline__ int block_detect_is64(const int* __restrict__ ei32,
                                                 int* sh_flag) {
    if (threadIdx.x < 32) {
        int w = ei32[2 * threadIdx.x + 1];
        unsigned any = __ballot_sync(0xFFFFFFFFu, w != 0);
        if (threadIdx.x == 0) *sh_flag = (any == 0u) ? 1 : 0;
    }
    __syncthreads();
    return *sh_flag;
}

__device__ __forceinline__ long long load_idx(const void* ei, size_t pos, int is64) {
    if (is64) return ((const long long*)ei)[pos];
    return (long long)((const int*)ei)[pos];
}

// ---------------------------------------------------------------------------
// Kernel A: fused prep. All writes are mutually independent:
//   blocks [0, RESET)         : winner[cell] = e   (plain-store election)
//   blocks [RESET, RESET+UV)  : u[node], v[node]   (warp-per-node dot)
//   blocks [RESET+UV, ...)    : zero out           (grid-stride 32B stores)
// Reset/UV first so their latency hides under the 604MB streaming zero.
// ---------------------------------------------------------------------------
__global__ void prep_kernel(longlong4* __restrict__ out, size_t n32,
                            const void* __restrict__ ei,
                            const float* __restrict__ z,
                            const float* __restrict__ W,
                            const float* __restrict__ b) {
    __shared__ int sh_flag;
    int bid = blockIdx.x;

    if (bid < RESET_BLOCKS) {
        int is64 = block_detect_is64((const int*)ei, &sh_flag);
        int e = bid * 256 + threadIdx.x;
        if (e >= N_EDGES) return;
        long long r = load_idx(ei, e, is64);
        long long c = load_idx(ei, (size_t)N_EDGES + e, is64);
        if ((unsigned long long)r >= N_NODES || (unsigned long long)c >= N_NODES) return;
        g_winner[(size_t)r * N_NODES + c] = e;   // race OK: any winner works
    } else if (bid < RESET_BLOCKS + UV_BLOCKS) {
        int node = (bid - RESET_BLOCKS) * 8 + (threadIdx.x >> 5);
        int lane = threadIdx.x & 31;
        if (node >= N_NODES) return;
        float4 zv = reinterpret_cast<const float4*>(z + (size_t)node * 128)[lane];
        float4 w1 = reinterpret_cast<const float4*>(W)[lane];
        float4 w2 = reinterpret_cast<const float4*>(W + 128)[lane];
        float s1 = zv.x * w1.x + zv.y * w1.y + zv.z * w1.z + zv.w * w1.w;
        float s2 = zv.x * w2.x + zv.y * w2.y + zv.z * w2.z + zv.w * w2.w;
        #pragma unroll
        for (int o = 16; o > 0; o >>= 1) {
            s1 += __shfl_xor_sync(0xFFFFFFFFu, s1, o);
            s2 += __shfl_xor_sync(0xFFFFFFFFu, s2, o);
        }
        if (lane == 0) {
            g_u[node] = s1 + b[0];   // fold bias into u
            g_v[node] = s2;
        }
    } else {
        size_t i = (size_t)(bid - RESET_BLOCKS - UV_BLOCKS) * blockDim.x + threadIdx.x;
        size_t stride = (size_t)ZERO_BLOCKS * blockDim.x;
        longlong4 zero = make_longlong4(0, 0, 0, 0);
        for (; i < n32; i += stride) out[i] = zero;
    }
}

// ---------------------------------------------------------------------------
// Kernel B: fused edge scatter. Thread-per-edge:
//   add = attr_sum + (winner[cell]==e ? u[r]+v[c] : 0)
//   atomicAdd(&out[cell], add)           -- single random RMW per edge
// winner[cell] is a plain coalesced-issue random LOAD (no RMW).
// ---------------------------------------------------------------------------
__global__ void edge_kernel(const void* __restrict__ ei,
                            const float4* __restrict__ attr,
                            float* __restrict__ out) {
    __shared__ int sh_flag;
    int is64 = block_detect_is64((const int*)ei, &sh_flag);

    int e = blockIdx.x * 256 + threadIdx.x;
    if (e >= N_EDGES) return;
    long long r = load_idx(ei, e, is64);
    long long c = load_idx(ei, (size_t)N_EDGES + e, is64);
    if ((unsigned long long)r >= N_NODES || (unsigned long long)c >= N_NODES) return;

    float4 a = attr[e];
    size_t cell = (size_t)r * N_NODES + c;

    float add = a.x + a.y + a.z + a.w;
    if (g_winner[cell] == e)            // elected edge adds p exactly once
        add += g_u[r] + g_v[c];
    atomicAdd(&out[cell], add);
}

// ---------------------------------------------------------------------------
extern "C" void kernel_launch(void* const* d_in, const int* in_sizes, int n_in,
                              void* d_out, int out_size) {
    const float*  z    = (const float*)d_in[0];
    const void*   ei   = d_in[1];
    const float4* attr = (const float4*)d_in[2];
    const float*  W    = (const float*)d_in[3];
    const float*  b    = (const float*)d_in[4];
    float*        out  = (float*)d_out;

    size_t n32 = (size_t)out_size / 8;   // output elems / 8 floats per 32B store

    prep_kernel<<<RESET_BLOCKS + UV_BLOCKS + ZERO_BLOCKS, 256>>>(
        (longlong4*)out, n32, ei, z, W, b);

    edge_kernel<<<(N_EDGES + 255) / 256, 256>>>(ei, attr, out);
}

// round 6
// speedup vs baseline: 1.4474x; 1.4474x over previous
#include <cuda_runtime.h>
#include <cuda_bf16.h>
#include <cstdint>

// Inputs (metadata order):
//   d_in[0] = z          float32 [12288, 128]
//   d_in[1] = edge_index int32 [2, 393216] (jnp.int64 silently downcast; detect)
//   d_in[2] = edge_attr  float32 [393216, 4]
//   d_in[3] = W          float32 [1, 256]
//   d_in[4] = b          float32 [1]
// Output: float32 [12288, 12288]
//
// out[r,c] = sum_dup(attr_sum) + (u[r] + v[c] + b) added ONCE per distinct cell.
// Duplicate edges share (r,c) => identical p => any single election winner
// yields the same output, so a plain-store race is a valid (deterministic-
// output) election.

#define N_NODES 12288
#define N_EDGES 393216

#define RESET_BLOCKS 1536   // 1536*256 = 393216 threads, one per edge
#define UV_BLOCKS    1536   // 1536*8 warps = 12288, one warp per node
#define ZERO_BLOCKS  4736   // 148 SMs * 32

// per-cell elected edge id (winner of the plain-store race in prep)
__device__ int g_winner[(size_t)N_NODES * N_NODES];
// per-node partial dots: u[i] = dot(z[i], W[0:128]) + b, v[i] = dot(z[i], W[128:256])
__device__ float g_u[N_NODES];
__device__ float g_v[N_NODES];

// ---------------------------------------------------------------------------
// In-block edge_index dtype detect: if data is int64, the odd int32 words are
// high halves of small non-negative indices => all zero. For int32 data they
// are random indices in [0,12288) — P(32 all zero) ~ 0. Warp-0 ballot.
// ---------------------------------------------------------------------------
__device__ __forceinline__ int block_detect_is64(const int* __restrict__ ei32,
                                                 int* sh_flag) {
    if (threadIdx.x < 32) {
        int w = ei32[2 * threadIdx.x + 1];
        unsigned any = __ballot_sync(0xFFFFFFFFu, w != 0);
        if (threadIdx.x == 0) *sh_flag = (any == 0u) ? 1 : 0;
    }
    __syncthreads();
    return *sh_flag;
}

__device__ __forceinline__ long long load_idx(const void* ei, size_t pos, int is64) {
    if (is64) return ((const long long*)ei)[pos];
    return (long long)((const int*)ei)[pos];
}

// ---------------------------------------------------------------------------
// Kernel A: fused prep. All writes are mutually independent:
//   blocks [0, RESET)         : winner[cell] = e   (plain-store election)
//   blocks [RESET, RESET+UV)  : u[node], v[node]   (warp-per-node dot)
//   blocks [RESET+UV, ...)    : zero out           (grid-stride float4 STG.128)
// Reset/UV first so their latency hides under the 604MB streaming zero.
// float4 (one STG.128/thread) is measurably faster than longlong4 (R5 lesson).
// ---------------------------------------------------------------------------
__global__ void prep_kernel(float4* __restrict__ out, size_t n4,
                            const void* __restrict__ ei,
                            const float* __restrict__ z,
                            const float* __restrict__ W,
                            const float* __restrict__ b) {
    __shared__ int sh_flag;
    int bid = blockIdx.x;

    if (bid < RESET_BLOCKS) {
        int is64 = block_detect_is64((const int*)ei, &sh_flag);
        int e = bid * 256 + threadIdx.x;
        if (e >= N_EDGES) return;
        long long r = load_idx(ei, e, is64);
        long long c = load_idx(ei, (size_t)N_EDGES + e, is64);
        if ((unsigned long long)r >= N_NODES || (unsigned long long)c >= N_NODES) return;
        g_winner[(size_t)r * N_NODES + c] = e;   // race OK: any winner works
    } else if (bid < RESET_BLOCKS + UV_BLOCKS) {
        int node = (bid - RESET_BLOCKS) * 8 + (threadIdx.x >> 5);
        int lane = threadIdx.x & 31;
        if (node >= N_NODES) return;
        float4 zv = reinterpret_cast<const float4*>(z + (size_t)node * 128)[lane];
        float4 w1 = reinterpret_cast<const float4*>(W)[lane];
        float4 w2 = reinterpret_cast<const float4*>(W + 128)[lane];
        float s1 = zv.x * w1.x + zv.y * w1.y + zv.z * w1.z + zv.w * w1.w;
        float s2 = zv.x * w2.x + zv.y * w2.y + zv.z * w2.z + zv.w * w2.w;
        #pragma unroll
        for (int o = 16; o > 0; o >>= 1) {
            s1 += __shfl_xor_sync(0xFFFFFFFFu, s1, o);
            s2 += __shfl_xor_sync(0xFFFFFFFFu, s2, o);
        }
        if (lane == 0) {
            g_u[node] = s1 + b[0];   // fold bias into u
            g_v[node] = s2;
        }
    } else {
        size_t i = (size_t)(bid - RESET_BLOCKS - UV_BLOCKS) * blockDim.x + threadIdx.x;
        size_t stride = (size_t)ZERO_BLOCKS * blockDim.x;
        float4 zero = make_float4(0.f, 0.f, 0.f, 0.f);
        for (; i < n4; i += stride) out[i] = zero;
    }
}

// ---------------------------------------------------------------------------
// Kernel B: fused edge scatter. Thread-per-edge:
//   add = attr_sum + (winner[cell]==e ? u[r]+v[c] : 0)
//   atomicAdd(&out[cell], add)           -- single random RMW per edge
// winner[cell] is a plain random LOAD (no RMW).
// ---------------------------------------------------------------------------
__global__ void edge_kernel(const void* __restrict__ ei,
                            const float4* __restrict__ attr,
                            float* __restrict__ out) {
    __shared__ int sh_flag;
    int is64 = block_detect_is64((const int*)ei, &sh_flag);

    int e = blockIdx.x * 256 + threadIdx.x;
    if (e >= N_EDGES) return;
    long long r = load_idx(ei, e, is64);
    long long c = load_idx(ei, (size_t)N_EDGES + e, is64);
    if ((unsigned long long)r >= N_NODES || (unsigned long long)c >= N_NODES) return;

    float4 a = attr[e];
    size_t cell = (size_t)r * N_NODES + c;

    float add = a.x + a.y + a.z + a.w;
    if (g_winner[cell] == e)            // elected edge adds p exactly once
        add += g_u[r] + g_v[c];
    atomicAdd(&out[cell], add);
}

// ---------------------------------------------------------------------------
extern "C" void kernel_launch(void* const* d_in, const int* in_sizes, int n_in,
                              void* d_out, int out_size) {
    const float*  z    = (const float*)d_in[0];
    const void*   ei   = d_in[1];
    const float4* attr = (const float4*)d_in[2];
    const float*  W    = (const float*)d_in[3];
    const float*  b    = (const float*)d_in[4];
    float*        out  = (float*)d_out;

    size_t n4 = (size_t)out_size / 4;

    prep_kernel<<<RESET_BLOCKS + UV_BLOCKS + ZERO_BLOCKS, 256>>>(
        (float4*)out, n4, ei, z, W, b);

    edge_kernel<<<(N_EDGES + 255) / 256, 256>>>(ei, attr, out);
}

// round 7
// speedup vs baseline: 1.5013x; 1.0372x over previous
#include <cuda_runtime.h>
#include <cuda_bf16.h>
#include <cstdint>

// Inputs (metadata order):
//   d_in[0] = z          float32 [12288, 128]
//   d_in[1] = edge_index int32 [2, 393216] (jnp.int64 silently downcast; detect)
//   d_in[2] = edge_attr  float32 [393216, 4]
//   d_in[3] = W          float32 [1, 256]
//   d_in[4] = b          float32 [1]
// Output: float32 [12288, 12288]
//
// out[r,c] = sum_dup(attr_sum) + (u[r]+v[c]+b) once per distinct cell.
// Strategy: edges accumulate into an L2-resident hash (keyed by cell id,
// dedup/election via atomicCAS insert), fused into the SAME kernel as the
// 604MB zero-fill so edge work hides under the streaming-write floor. A tiny
// scatter pass then plain-stores hash entries into the zeroed output.

#define N_NODES 12288
#define N_EDGES 393216

#define UV_BLOCKS    1536   // 1536*8 warps = 12288, one warp per node
#define CLEAR_BLOCKS 2048   // 2048*256 threads clear HASH_SIZE/4 int4+float4
#define EDGE_BLOCKS  1536   // thread per edge
#define ZERO_BLOCKS  4736   // 148 SMs * 32

#define HASH_BITS 21
#define HASH_SIZE (1u << HASH_BITS)         // 2,097,152 slots (load ~0.19)
#define HASH_MASK (HASH_SIZE - 1u)

__device__ int   g_keys[HASH_SIZE];         // cell id or -1 (empty); 8 MB
__device__ float g_vals[HASH_SIZE];         // accumulated value;      8 MB
__device__ float g_u[N_NODES];              // dot(z[i], W[0:128]) + b
__device__ float g_v[N_NODES];              // dot(z[i], W[128:256])

// ---------------------------------------------------------------------------
// In-block edge_index dtype detect (int64 => odd int32 words all zero).
// ---------------------------------------------------------------------------
__device__ __forceinline__ int block_detect_is64(const int* __restrict__ ei32,
                                                 int* sh_flag) {
    if (threadIdx.x < 32) {
        int w = ei32[2 * threadIdx.x + 1];
        unsigned any = __ballot_sync(0xFFFFFFFFu, w != 0);
        if (threadIdx.x == 0) *sh_flag = (any == 0u) ? 1 : 0;
    }
    __syncthreads();
    return *sh_flag;
}

__device__ __forceinline__ long long load_idx(const void* ei, size_t pos, int is64) {
    if (is64) return ((const long long*)ei)[pos];
    return (long long)((const int*)ei)[pos];
}

// ---------------------------------------------------------------------------
// Kernel 1: init. Independent block ranges:
//   [0, UV)            : u[node], v[node] (warp-per-node dot, bias folded in u)
//   [UV, UV+CLEAR)     : keys = -1, vals = 0 (16B stores)
// ---------------------------------------------------------------------------
__global__ void init_kernel(const float* __restrict__ z,
                            const float* __restrict__ W,
                            const float* __restrict__ b) {
    int bid = blockIdx.x;
    if (bid < UV_BLOCKS) {
        int node = bid * 8 + (threadIdx.x >> 5);
        int lane = threadIdx.x & 31;
        if (node >= N_NODES) return;
        float4 zv = reinterpret_cast<const float4*>(z + (size_t)node * 128)[lane];
        float4 w1 = reinterpret_cast<const float4*>(W)[lane];
        float4 w2 = reinterpret_cast<const float4*>(W + 128)[lane];
        float s1 = zv.x * w1.x + zv.y * w1.y + zv.z * w1.z + zv.w * w1.w;
        float s2 = zv.x * w2.x + zv.y * w2.y + zv.z * w2.z + zv.w * w2.w;
        #pragma unroll
        for (int o = 16; o > 0; o >>= 1) {
            s1 += __shfl_xor_sync(0xFFFFFFFFu, s1, o);
            s2 += __shfl_xor_sync(0xFFFFFFFFu, s2, o);
        }
        if (lane == 0) {
            g_u[node] = s1 + b[0];
            g_v[node] = s2;
        }
    } else {
        unsigned t = (unsigned)(bid - UV_BLOCKS) * 256u + threadIdx.x;  // < HASH_SIZE/4
        reinterpret_cast<int4*>(g_keys)[t]   = make_int4(-1, -1, -1, -1);
        reinterpret_cast<float4*>(g_vals)[t] = make_float4(0.f, 0.f, 0.f, 0.f);
    }
}

// ---------------------------------------------------------------------------
// Kernel 2: mega. Edge blocks FIRST (start early, hide under zero stream):
//   [0, EDGE)      : hash-insert cell (atomicCAS election) + atomicAdd value
//   [EDGE, ...)    : zero out, grid-stride float4 (one STG.128/thread)
// ---------------------------------------------------------------------------
__global__ void mega_kernel(float4* __restrict__ out, size_t n4,
                            const void* __restrict__ ei,
                            const float4* __restrict__ attr) {
    __shared__ int sh_flag;
    int bid = blockIdx.x;

    if (bid < EDGE_BLOCKS) {
        int is64 = block_detect_is64((const int*)ei, &sh_flag);
        int e = bid * 256 + threadIdx.x;
        if (e >= N_EDGES) return;
        long long r = load_idx(ei, e, is64);
        long long c = load_idx(ei, (size_t)N_EDGES + e, is64);
        if ((unsigned long long)r >= N_NODES || (unsigned long long)c >= N_NODES) return;

        float4 a = attr[e];
        int cell = (int)(r * N_NODES + c);              // < 2^31, fits int
        float add = a.x + a.y + a.z + a.w;

        // linear-probe insert; inserter (elected) also adds p once
        unsigned h = ((unsigned)cell * 2654435761u) >> (32 - HASH_BITS);
        while (true) {
            int prev = atomicCAS(&g_keys[h], -1, cell);
            if (prev == -1) { add += g_u[r] + g_v[c]; break; }   // elected
            if (prev == cell) break;                             // duplicate
            h = (h + 1u) & HASH_MASK;
        }
        atomicAdd(&g_vals[h], add);
    } else {
        size_t i = (size_t)(bid - EDGE_BLOCKS) * blockDim.x + threadIdx.x;
        size_t stride = (size_t)ZERO_BLOCKS * blockDim.x;
        float4 zero = make_float4(0.f, 0.f, 0.f, 0.f);
        for (; i < n4; i += stride) out[i] = zero;
    }
}

// ---------------------------------------------------------------------------
// Kernel 3: scatter hash -> out. Each occupied slot owns its cell uniquely,
// and the cell was zeroed in kernel 2 => plain store, no RMW.
// ---------------------------------------------------------------------------
__global__ void scatter_kernel(float* __restrict__ out) {
    unsigned t = blockIdx.x * 256u + threadIdx.x;
    if (t >= HASH_SIZE) return;
    int k = g_keys[t];
    if (k >= 0) out[(size_t)(unsigned)k] = g_vals[t];
}

// ---------------------------------------------------------------------------
extern "C" void kernel_launch(void* const* d_in, const int* in_sizes, int n_in,
                              void* d_out, int out_size) {
    const float*  z    = (const float*)d_in[0];
    const void*   ei   = d_in[1];
    const float4* attr = (const float4*)d_in[2];
    const float*  W    = (const float*)d_in[3];
    const float*  b    = (const float*)d_in[4];
    float*        out  = (float*)d_out;

    size_t n4 = (size_t)out_size / 4;

    init_kernel<<<UV_BLOCKS + CLEAR_BLOCKS, 256>>>(z, W, b);
    mega_kernel<<<EDGE_BLOCKS + ZERO_BLOCKS, 256>>>((float4*)out, n4, ei, attr);
    scatter_kernel<<<(HASH_SIZE + 255) / 256, 256>>>(out);
}

// round 8
// speedup vs baseline: 1.5240x; 1.0151x over previous
#include <cuda_runtime.h>
#include <cuda_bf16.h>
#include <cstdint>

// Inputs (metadata order):
//   d_in[0] = z          float32 [12288, 128]
//   d_in[1] = edge_index int32 [2, 393216] (jnp.int64 silently downcast; detect)
//   d_in[2] = edge_attr  float32 [393216, 4]
//   d_in[3] = W          float32 [1, 256]
//   d_in[4] = b          float32 [1]
// Output: float32 [12288, 12288]
//
// out[r,c] = sum_dup(attr_sum) + (u[r]+v[c]+b) once per distinct cell.
// Edges accumulate into an L2-resident hash (key = cell+1, 0 = empty, election
// via atomicCAS insert), fused into the same kernel as the 604MB zero-fill so
// edge work hides under the streaming-write floor. Scatter pass plain-stores
// hash entries into the zeroed output AND restores the slots it read to zero,
// so the hash is self-cleaning (zero-init at module load = empty; no clear
// kernel needed, deterministic across graph replays).

#define N_NODES 12288
#define N_EDGES 393216

#define UV_BLOCKS    1536   // 1536*8 warps = 12288, one warp per node
#define EDGE_BLOCKS  1536   // thread per edge
#define ZERO_BLOCKS  4736   // 148 SMs * 32

#define HASH_BITS 20
#define HASH_SIZE (1u << HASH_BITS)         // 1,048,576 slots (load ~0.37)
#define HASH_MASK (HASH_SIZE - 1u)

__device__ int   g_keys[HASH_SIZE];         // cell+1, 0 = empty; 4 MB; zero-init
__device__ float g_vals[HASH_SIZE];         // accumulated value; 4 MB; zero-init
__device__ float g_u[N_NODES];              // dot(z[i], W[0:128]) + b
__device__ float g_v[N_NODES];              // dot(z[i], W[128:256])

// ---------------------------------------------------------------------------
// In-block edge_index dtype detect (int64 => odd int32 words all zero).
// ---------------------------------------------------------------------------
__device__ __forceinline__ int block_detect_is64(const int* __restrict__ ei32,
                                                 int* sh_flag) {
    if (threadIdx.x < 32) {
        int w = ei32[2 * threadIdx.x + 1];
        unsigned any = __ballot_sync(0xFFFFFFFFu, w != 0);
        if (threadIdx.x == 0) *sh_flag = (any == 0u) ? 1 : 0;
    }
    __syncthreads();
    return *sh_flag;
}

__device__ __forceinline__ long long load_idx(const void* ei, size_t pos, int is64) {
    if (is64) return ((const long long*)ei)[pos];
    return (long long)((const int*)ei)[pos];
}

// ---------------------------------------------------------------------------
// Kernel 1: u/v precompute only (hash needs no clearing — self-cleaning).
// Warp-per-node dot; bias folded into u.
// ---------------------------------------------------------------------------
__global__ void init_kernel(const float* __restrict__ z,
                            const float* __restrict__ W,
                            const float* __restrict__ b) {
    int node = blockIdx.x * 8 + (threadIdx.x >> 5);
    int lane = threadIdx.x & 31;
    if (node >= N_NODES) return;
    float4 zv = reinterpret_cast<const float4*>(z + (size_t)node * 128)[lane];
    float4 w1 = reinterpret_cast<const float4*>(W)[lane];
    float4 w2 = reinterpret_cast<const float4*>(W + 128)[lane];
    float s1 = zv.x * w1.x + zv.y * w1.y + zv.z * w1.z + zv.w * w1.w;
    float s2 = zv.x * w2.x + zv.y * w2.y + zv.z * w2.z + zv.w * w2.w;
    #pragma unroll
    for (int o = 16; o > 0; o >>= 1) {
        s1 += __shfl_xor_sync(0xFFFFFFFFu, s1, o);
        s2 += __shfl_xor_sync(0xFFFFFFFFu, s2, o);
    }
    if (lane == 0) {
        g_u[node] = s1 + b[0];
        g_v[node] = s2;
    }
}

// ---------------------------------------------------------------------------
// Kernel 2: mega. Edge blocks FIRST (start early, hide under zero stream):
//   [0, EDGE)   : hash-insert cell+1 (atomicCAS election) + atomicAdd value
//   [EDGE, ...) : zero out, grid-stride float4 (one STG.128/thread)
// ---------------------------------------------------------------------------
__global__ void mega_kernel(float4* __restrict__ out, size_t n4,
                            const void* __restrict__ ei,
                            const float4* __restrict__ attr) {
    __shared__ int sh_flag;
    int bid = blockIdx.x;

    if (bid < EDGE_BLOCKS) {
        int is64 = block_detect_is64((const int*)ei, &sh_flag);
        int e = bid * 256 + threadIdx.x;
        if (e >= N_EDGES) return;
        long long r = load_idx(ei, e, is64);
        long long c = load_idx(ei, (size_t)N_EDGES + e, is64);
        if ((unsigned long long)r >= N_NODES || (unsigned long long)c >= N_NODES) return;

        float4 a = attr[e];
        int key = (int)(r * N_NODES + c) + 1;           // 0 reserved for empty
        float add = a.x + a.y + a.z + a.w;

        // linear-probe insert; inserter (elected) also adds p once
        unsigned h = ((unsigned)key * 2654435761u) >> (32 - HASH_BITS);
        while (true) {
            int prev = atomicCAS(&g_keys[h], 0, key);
            if (prev == 0)  { add += g_u[r] + g_v[c]; break; }   // elected
            if (prev == key) break;                              // duplicate
            h = (h + 1u) & HASH_MASK;
        }
        atomicAdd(&g_vals[h], add);
    } else {
        size_t i = (size_t)(bid - EDGE_BLOCKS) * blockDim.x + threadIdx.x;
        size_t stride = (size_t)ZERO_BLOCKS * blockDim.x;
        float4 zero = make_float4(0.f, 0.f, 0.f, 0.f);
        for (; i < n4; i += stride) out[i] = zero;
    }
}

// ---------------------------------------------------------------------------
// Kernel 3: scatter hash -> out, then restore slots to empty (self-cleaning).
// Each occupied slot owns its cell uniquely; cell was zeroed in kernel 2
// => plain store, no RMW. Restore writes only touch occupied slots.
// ---------------------------------------------------------------------------
__global__ void scatter_kernel(float* __restrict__ out) {
    unsigned t = blockIdx.x * 256u + threadIdx.x;
    if (t >= HASH_SIZE) return;
    int k = g_keys[t];
    if (k > 0) {
        out[(size_t)(unsigned)(k - 1)] = g_vals[t];
        g_keys[t] = 0;      // restore empty for next launch / graph replay
        g_vals[t] = 0.0f;
    }
}

// ---------------------------------------------------------------------------
extern "C" void kernel_launch(void* const* d_in, const int* in_sizes, int n_in,
                              void* d_out, int out_size) {
    const float*  z    = (const float*)d_in[0];
    const void*   ei   = d_in[1];
    const float4* attr = (const float4*)d_in[2];
    const float*  W    = (const float*)d_in[3];
    const float*  b    = (const float*)d_in[4];
    float*        out  = (float*)d_out;

    size_t n4 = (size_t)out_size / 4;

    init_kernel<<<UV_BLOCKS, 256>>>(z, W, b);
    mega_kernel<<<EDGE_BLOCKS + ZERO_BLOCKS, 256>>>((float4*)out, n4, ei, attr);
    scatter_kernel<<<(HASH_SIZE + 255) / 256, 256>>>(out);
}